// round 7
// baseline (speedup 1.0000x reference)
#include <cuda_runtime.h>
#include <math.h>

#define NBINS 256
#define HW    50176          // 224*224
#define NB    8
#define EPSF  1e-10f
#define WCUT  1e-4f          // atomic-skip cut; dropped mass ~2e-5 relative
#define TABN  512            // lerp table resolution

// Scratch (__device__ globals are zero-initialized at module load; kernels
// below restore them to zero after use, so every graph replay sees zeros).
__device__ float g_joint[NB * NBINS * NBINS];   // 2 MB
__device__ float g_m1[NB * NBINS];
__device__ float g_m2[NB * NBINS];
__device__ float g_s1[NB], g_s2[NB], g_sj[NB];  // analytic normalizers
__device__ float g_hj[NB];                      // joint  Σ v·log2 v partials
__device__ float g_h1[NB], g_h2[NB];            // marginal entropy (plain store)

// ---------------------------------------------------------------------------
template <int NW>
__device__ __forceinline__ float blk_sum(float v, float* swarp) {
    __syncthreads();                 // protect swarp reuse across calls
#pragma unroll
    for (int o = 16; o >= 1; o >>= 1) v += __shfl_xor_sync(0xffffffffu, v, o);
    if ((threadIdx.x & 31) == 0) swarp[threadIdx.x >> 5] = v;
    __syncthreads();
    float r = 0.0f;
#pragma unroll
    for (int i = 0; i < NW; i++) r += swarp[i];
    return r;
}

// ---------------------------------------------------------------------------
// K1: sparse Parzen accumulation, table-lerp weights.
// Only bins floor(x) and floor(x)+1 carry non-negligible weight.
// Weights below WCUT are dropped from the scatter (normalizers keep the full
// analytic mass, matching the reference normalization).
// Grid (49, NB), block 512, 2 px/thread via float2  (42 warps/SM for latency
// hiding of ATOMS/REDG).
// ---------------------------------------------------------------------------
__global__ void __launch_bounds__(512) mi_accum(const float2* __restrict__ in1,
                                                const float2* __restrict__ in2) {
    __shared__ float2 s_tab[TABN + 1];
    __shared__ float s_m1[NBINS];
    __shared__ float s_m2[NBINS];
    __shared__ float s16[16];

    const int b = blockIdx.y;
    const int t = threadIdx.x;

    // Per-CTA table generation: ~2 __expf per thread.
    for (int k = t; k <= TABN; k += 512) {
        float f = (float)k * (1.0f / TABN);
        float g = 1.0f - f;
        s_tab[k] = make_float2(__expf(-50.0f * f * f), __expf(-50.0f * g * g));
    }
    if (t < NBINS) { s_m1[t] = 0.0f; s_m2[t] = 0.0f; }
    __syncthreads();

    const int idx = blockIdx.x * 512 + t;            // float2 index in image
    const float2 v1 = in1[b * (HW / 2) + idx];
    const float2 v2 = in2[b * (HW / 2) + idx];

    float* __restrict__ joint = g_joint + (size_t)b * NBINS * NBINS;
    float sw1 = 0.0f, sw2 = 0.0f, swj = 0.0f;

    const float* p1v = (const float*)&v1;
    const float* p2v = (const float*)&v2;
#pragma unroll
    for (int k = 0; k < 2; k++) {
        // x in [0,255); u = x*TABN; kg = floor(u); i0 = kg>>9; ki = kg&511
        float u1 = p1v[k] * (255.0f * TABN);
        float u2 = p2v[k] * (255.0f * TABN);
        int kg1 = __float2int_rd(u1);
        int kg2 = __float2int_rd(u2);
        int i0 = kg1 >> 9;            // floor(x1), in [0,254]
        int j0 = kg2 >> 9;
        int ki1 = kg1 & (TABN - 1);
        int ki2 = kg2 & (TABN - 1);
        float fr1 = u1 - (float)kg1;
        float fr2 = u2 - (float)kg2;

        float2 A0 = s_tab[ki1], A1 = s_tab[ki1 + 1];
        float2 B0 = s_tab[ki2], B1 = s_tab[ki2 + 1];
        float w1a = fmaf(fr1, A1.x - A0.x, A0.x);
        float w1b = fmaf(fr1, A1.y - A0.y, A0.y);
        float w2a = fmaf(fr2, B1.x - B0.x, B0.x);
        float w2b = fmaf(fr2, B1.y - B0.y, B0.y);

        float t1 = w1a + w1b, t2 = w2a + w2b;
        sw1 += t1; sw2 += t2; swj += t1 * t2;

        if (w1a > WCUT) atomicAdd(&s_m1[i0],     w1a);
        if (w1b > WCUT) atomicAdd(&s_m1[i0 + 1], w1b);
        if (w2a > WCUT) atomicAdd(&s_m2[j0],     w2a);
        if (w2b > WCUT) atomicAdd(&s_m2[j0 + 1], w2b);

        float p;
        p = w1a * w2a; if (p > WCUT) atomicAdd(&joint[i0 * NBINS + j0],           p);
        p = w1a * w2b; if (p > WCUT) atomicAdd(&joint[i0 * NBINS + j0 + 1],       p);
        p = w1b * w2a; if (p > WCUT) atomicAdd(&joint[(i0 + 1) * NBINS + j0],     p);
        p = w1b * w2b; if (p > WCUT) atomicAdd(&joint[(i0 + 1) * NBINS + j0 + 1], p);
    }

    float S1 = blk_sum<16>(sw1, s16);
    float S2 = blk_sum<16>(sw2, s16);
    float SJ = blk_sum<16>(swj, s16);
    if (t == 0) {
        atomicAdd(&g_s1[b], S1);
        atomicAdd(&g_s2[b], S2);
        atomicAdd(&g_sj[b], SJ);
    }

    // flush marginal histograms (one global atomic per bin per CTA)
    if (t < NBINS) {
        if (s_m1[t] != 0.0f) atomicAdd(&g_m1[b * NBINS + t], s_m1[t]);
        if (s_m2[t] != 0.0f) atomicAdd(&g_m2[b * NBINS + t], s_m2[t]);
    }
}

// ---------------------------------------------------------------------------
// K2: entropies. Grid (33, NB), block 256.
//  cx in [0,32): 2048 joint entries each; accumulates Σ v·log2(v) (v>0),
//                re-zeroes its chunk.
//  cx == 32:     both marginal entropies, re-zeroes g_m1/g_m2.
// ---------------------------------------------------------------------------
__global__ void __launch_bounds__(256) mi_entropy() {
    __shared__ float s8[8];
    const int b = blockIdx.y;
    const int cx = blockIdx.x;
    const int t = threadIdx.x;

    if (cx < 32) {
        float4* __restrict__ j4 =
            (float4*)(g_joint + (size_t)b * NBINS * NBINS) + cx * 512;

        float hj = 0.0f;     // Sum of v * log2(v) over nonzero v
#pragma unroll
        for (int k = 0; k < 2; k++) {
            float4 v = j4[k * 256 + t];
            if (v.x > 0.0f) hj += v.x * __log2f(v.x);
            if (v.y > 0.0f) hj += v.y * __log2f(v.y);
            if (v.z > 0.0f) hj += v.z * __log2f(v.z);
            if (v.w > 0.0f) hj += v.w * __log2f(v.w);
            j4[k * 256 + t] = make_float4(0.0f, 0.0f, 0.0f, 0.0f);  // re-zero
        }
        float HJ = blk_sum<8>(hj, s8);
        if (t == 0) atomicAdd(&g_hj[b], HJ);
    } else {
        const float invHW = 1.0f / (float)HW;
        // marginal 1
        float q1 = g_m1[b * NBINS + t] * invHW;
        float n1 = g_s1[b] * invHW + EPSF;
        float pm1 = q1 / n1;
        float H1 = blk_sum<8>(pm1 * __log2f(pm1 + EPSF), s8);
        // marginal 2
        float q2 = g_m2[b * NBINS + t] * invHW;
        float n2 = g_s2[b] * invHW + EPSF;
        float pm2 = q2 / n2;
        float H2 = blk_sum<8>(pm2 * __log2f(pm2 + EPSF), s8);
        if (t == 0) { g_h1[b] = H1; g_h2[b] = H2; }
        g_m1[b * NBINS + t] = 0.0f;                    // re-zero for next replay
        g_m2[b * NBINS + t] = 0.0f;
    }
}

// ---------------------------------------------------------------------------
// K3: final MI. Converts joint Σ v·log2 v into the joint entropy:
//   Hj = -(1/Sj)·Σ v·log2 v + log2(Sj)      (eps effect negligible)
// and restores atomic scratch to zero.
// ---------------------------------------------------------------------------
__global__ void mi_final(float* __restrict__ out) {
    int b = threadIdx.x;
    if (b < NB) {
        float Sj = g_sj[b] + EPSF;
        float HJ = -g_hj[b] / Sj + __log2f(Sj);
        float H1 = -g_h1[b], H2 = -g_h2[b];
        float mi = H1 + H2 - HJ;
        out[b] = 2.0f * mi / (H1 + H2);   // NORMALIZE = True
        g_hj[b] = 0.0f;
        g_s1[b] = 0.0f; g_s2[b] = 0.0f; g_sj[b] = 0.0f;
    }
}

// ---------------------------------------------------------------------------
extern "C" void kernel_launch(void* const* d_in, const int* in_sizes, int n_in,
                              void* d_out, int out_size) {
    const float2* in1 = (const float2*)d_in[0];
    const float2* in2 = (const float2*)d_in[1];
    // d_in[2] = bins (exactly 0..255) folded in analytically.
    float* out = (float*)d_out;

    mi_accum<<<dim3(49, NB), 512>>>(in1, in2);
    mi_entropy<<<dim3(33, NB), 256>>>();
    mi_final<<<1, 32>>>(out);
}

// round 9
// speedup vs baseline: 1.0551x; 1.0551x over previous
#include <cuda_runtime.h>
#include <cstdint>
#include <math.h>

#define NBINS 256
#define HW    50176          // 224*224
#define NB    8
#define EPSF  1e-10f
#define WCUT  1e-4f          // atomic-skip cut; dropped mass ~2e-5 relative
#define TABN  512            // lerp table resolution

// Scratch (__device__ globals are zero-initialized at module load; kernels
// below restore them to zero after use, so every graph replay sees zeros).
__device__ float g_joint[NB * NBINS * NBINS];   // 2 MB
__device__ float g_m1[NB * NBINS];
__device__ float g_m2[NB * NBINS];
__device__ float g_s1[NB], g_s2[NB], g_sj[NB];  // analytic normalizers
__device__ float g_hj[NB];                      // joint  Σ v·log2 v partials
__device__ float g_h1[NB], g_h2[NB];            // marginal entropy (plain store)

// ---------------------------------------------------------------------------
// Predicated reductions: single @p red instruction, no BSSY/BSYNC branch
// scaffolding (ptxas never emits this form from C++ if{}).
// ---------------------------------------------------------------------------
__device__ __forceinline__ uint32_t s2u(const void* p) {
    uint32_t a;
    asm("{ .reg .u64 t; cvta.to.shared.u64 t, %1; cvt.u32.u64 %0, t; }"
        : "=r"(a) : "l"(p));
    return a;
}

__device__ __forceinline__ void red_sh_if(uint32_t addr, float v, float cut) {
    asm volatile(
        "{ .reg .pred p; setp.gt.f32 p, %1, %2;\n\t"
        "@p red.shared.add.f32 [%0], %1; }"
        :: "r"(addr), "f"(v), "f"(cut) : "memory");
}

__device__ __forceinline__ void red_gl_if(float* addr, float v, float cut) {
    asm volatile(
        "{ .reg .pred p; setp.gt.f32 p, %1, %2;\n\t"
        "@p red.global.add.f32 [%0], %1; }"
        :: "l"(addr), "f"(v), "f"(cut) : "memory");
}

// ---------------------------------------------------------------------------
template <int NW>
__device__ __forceinline__ float blk_sum(float v, float* swarp) {
    __syncthreads();                 // protect swarp reuse across calls
#pragma unroll
    for (int o = 16; o >= 1; o >>= 1) v += __shfl_xor_sync(0xffffffffu, v, o);
    if ((threadIdx.x & 31) == 0) swarp[threadIdx.x >> 5] = v;
    __syncthreads();
    float r = 0.0f;
#pragma unroll
    for (int i = 0; i < NW; i++) r += swarp[i];
    return r;
}

// ---------------------------------------------------------------------------
// K1: sparse Parzen accumulation, table-lerp weights, predicated reds.
// Grid (49, NB), block 256, 4 px/thread via float4.
// ---------------------------------------------------------------------------
__global__ void __launch_bounds__(256) mi_accum(const float4* __restrict__ in1,
                                                const float4* __restrict__ in2) {
    __shared__ float2 s_tab[TABN + 1];
    __shared__ float s_m1[NBINS];
    __shared__ float s_m2[NBINS];
    __shared__ float s8[8];

    const int b = blockIdx.y;
    const int t = threadIdx.x;

    // Per-CTA table generation: 4 __expf per thread.
    for (int k = t; k <= TABN; k += 256) {
        float f = (float)k * (1.0f / TABN);
        float g = 1.0f - f;
        s_tab[k] = make_float2(__expf(-50.0f * f * f), __expf(-50.0f * g * g));
    }
    s_m1[t] = 0.0f;
    s_m2[t] = 0.0f;
    __syncthreads();

    const uint32_t m1b = s2u(s_m1);
    const uint32_t m2b = s2u(s_m2);

    const int idx = blockIdx.x * 256 + t;            // float4 index in image
    const float4 v1 = in1[b * (HW / 4) + idx];
    const float4 v2 = in2[b * (HW / 4) + idx];

    float* __restrict__ joint = g_joint + (size_t)b * NBINS * NBINS;
    float sw1 = 0.0f, sw2 = 0.0f, swj = 0.0f;

    const float* p1v = (const float*)&v1;
    const float* p2v = (const float*)&v2;
#pragma unroll
    for (int k = 0; k < 4; k++) {
        // x in [0,255); u = x*TABN; kg = floor(u); i0 = kg>>9; ki = kg&511
        float u1 = p1v[k] * (255.0f * TABN);
        float u2 = p2v[k] * (255.0f * TABN);
        int kg1 = __float2int_rd(u1);
        int kg2 = __float2int_rd(u2);
        int i0 = kg1 >> 9;            // floor(x1), in [0,254]
        int j0 = kg2 >> 9;
        int ki1 = kg1 & (TABN - 1);
        int ki2 = kg2 & (TABN - 1);
        float fr1 = u1 - (float)kg1;
        float fr2 = u2 - (float)kg2;

        float2 A0 = s_tab[ki1], A1 = s_tab[ki1 + 1];
        float2 B0 = s_tab[ki2], B1 = s_tab[ki2 + 1];
        float w1a = fmaf(fr1, A1.x - A0.x, A0.x);
        float w1b = fmaf(fr1, A1.y - A0.y, A0.y);
        float w2a = fmaf(fr2, B1.x - B0.x, B0.x);
        float w2b = fmaf(fr2, B1.y - B0.y, B0.y);

        float t1 = w1a + w1b, t2 = w2a + w2b;
        sw1 += t1; sw2 += t2; swj += t1 * t2;

        red_sh_if(m1b + i0 * 4,       w1a, WCUT);
        red_sh_if(m1b + (i0 + 1) * 4, w1b, WCUT);
        red_sh_if(m2b + j0 * 4,       w2a, WCUT);
        red_sh_if(m2b + (j0 + 1) * 4, w2b, WCUT);

        float* jp = joint + i0 * NBINS + j0;
        red_gl_if(jp,             w1a * w2a, WCUT);
        red_gl_if(jp + 1,         w1a * w2b, WCUT);
        red_gl_if(jp + NBINS,     w1b * w2a, WCUT);
        red_gl_if(jp + NBINS + 1, w1b * w2b, WCUT);
    }

    float S1 = blk_sum<8>(sw1, s8);
    float S2 = blk_sum<8>(sw2, s8);
    float SJ = blk_sum<8>(swj, s8);
    if (t == 0) {
        atomicAdd(&g_s1[b], S1);
        atomicAdd(&g_s2[b], S2);
        atomicAdd(&g_sj[b], SJ);
    }

    __syncthreads();      // s_m1/s_m2 complete before flush
    // flush marginal histograms (one predicated global red per bin per CTA)
    red_gl_if(&g_m1[b * NBINS + t], s_m1[t], 0.0f);
    red_gl_if(&g_m2[b * NBINS + t], s_m2[t], 0.0f);
}

// ---------------------------------------------------------------------------
// K2: entropies. Grid (33, NB), block 256.
//  cx in [0,32): 2048 joint entries each; accumulates Σ v·log2(v),
//                re-zeroes its chunk. Branch-free: v·log2(v+1e-37) (=0 at v=0).
//  cx == 32:     both marginal entropies, re-zeroes g_m1/g_m2.
// ---------------------------------------------------------------------------
__global__ void __launch_bounds__(256) mi_entropy() {
    __shared__ float s8[8];
    const int b = blockIdx.y;
    const int cx = blockIdx.x;
    const int t = threadIdx.x;

    if (cx < 32) {
        float4* __restrict__ j4 =
            (float4*)(g_joint + (size_t)b * NBINS * NBINS) + cx * 512;

        float hj = 0.0f;     // Sum of v * log2(v)
#pragma unroll
        for (int k = 0; k < 2; k++) {
            float4 v = j4[k * 256 + t];
            hj += v.x * __log2f(v.x + 1e-37f);
            hj += v.y * __log2f(v.y + 1e-37f);
            hj += v.z * __log2f(v.z + 1e-37f);
            hj += v.w * __log2f(v.w + 1e-37f);
            j4[k * 256 + t] = make_float4(0.0f, 0.0f, 0.0f, 0.0f);  // re-zero
        }
        float HJ = blk_sum<8>(hj, s8);
        if (t == 0) atomicAdd(&g_hj[b], HJ);
    } else {
        const float invHW = 1.0f / (float)HW;
        // marginal 1
        float q1 = g_m1[b * NBINS + t] * invHW;
        float n1 = g_s1[b] * invHW + EPSF;
        float pm1 = q1 / n1;
        float H1 = blk_sum<8>(pm1 * __log2f(pm1 + EPSF), s8);
        // marginal 2
        float q2 = g_m2[b * NBINS + t] * invHW;
        float n2 = g_s2[b] * invHW + EPSF;
        float pm2 = q2 / n2;
        float H2 = blk_sum<8>(pm2 * __log2f(pm2 + EPSF), s8);
        if (t == 0) { g_h1[b] = H1; g_h2[b] = H2; }
        g_m1[b * NBINS + t] = 0.0f;                    // re-zero for next replay
        g_m2[b * NBINS + t] = 0.0f;
    }
}

// ---------------------------------------------------------------------------
// K3: final MI. Hj = -(1/Sj)·Σ v·log2 v + log2(Sj); resets atomic scratch.
// ---------------------------------------------------------------------------
__global__ void mi_final(float* __restrict__ out) {
    int b = threadIdx.x;
    if (b < NB) {
        float Sj = g_sj[b] + EPSF;
        float HJ = -g_hj[b] / Sj + __log2f(Sj);
        float H1 = -g_h1[b], H2 = -g_h2[b];
        float mi = H1 + H2 - HJ;
        out[b] = 2.0f * mi / (H1 + H2);   // NORMALIZE = True
        g_hj[b] = 0.0f;
        g_s1[b] = 0.0f; g_s2[b] = 0.0f; g_sj[b] = 0.0f;
    }
}

// ---------------------------------------------------------------------------
extern "C" void kernel_launch(void* const* d_in, const int* in_sizes, int n_in,
                              void* d_out, int out_size) {
    const float4* in1 = (const float4*)d_in[0];
    const float4* in2 = (const float4*)d_in[1];
    // d_in[2] = bins (exactly 0..255) folded in analytically.
    float* out = (float*)d_out;

    mi_accum<<<dim3(49, NB), 256>>>(in1, in2);
    mi_entropy<<<dim3(33, NB), 256>>>();
    mi_final<<<1, 32>>>(out);
}